// round 13
// baseline (speedup 1.0000x reference)
#include <cuda_runtime.h>
#include <cuda_bf16.h>
#include <math.h>
#include <stdint.h>

#define BSZ 2
#define SEQ 2048
#define DMODEL 2048
#define NHEADS 16
#define HDIM 128
#define NROWS (BSZ*SEQ)     // 4096
#define WSZ (DMODEL*DMODEL)
#define KBLKS (DMODEL/8)    // 256 k8-blocks per row
#define NB2T (DMODEL/16)    // 128 n16-blocks

// Scratch (allocation-free rule: __device__ globals)
__device__ float    g_q[BSZ*NHEADS*SEQ*HDIM];
__device__ float    g_k[BSZ*NHEADS*SEQ*HDIM];
__device__ float    g_v[BSZ*NHEADS*SEQ*HDIM];
__device__ uint32_t g_xp[(size_t)NROWS*DMODEL];   // x, tf32 bits, A-fragment-permuted
__device__ uint32_t g_wp[(size_t)4*WSZ];          // Wq,Wk,Wv,Wo tf32 bits, B-fragment-permuted
__device__ uint32_t g_cp[(size_t)NROWS*DMODEL];   // ctx, tf32 bits, A-fragment-permuted
// attention operands, pre-split bf16 hi/lo packed words, FRAGMENT-PERMUTED:
//   q: A-perm  [bh][mb16][kb8][lane][4w]
//   k: B-perm  [bh][nb16][kb8][lane][4w]
//   v: B-perm over d, k-dim = tpairs  [bh][dnb16][kb8][lane][4w]
__device__ uint32_t g_qh[(size_t)BSZ*NHEADS*SEQ*64];
__device__ uint32_t g_ql[(size_t)BSZ*NHEADS*SEQ*64];
__device__ uint32_t g_kh[(size_t)BSZ*NHEADS*SEQ*64];
__device__ uint32_t g_kl[(size_t)BSZ*NHEADS*SEQ*64];
__device__ uint32_t g_vth[(size_t)BSZ*NHEADS*HDIM*(SEQ/2)];
__device__ uint32_t g_vtl[(size_t)BSZ*NHEADS*HDIM*(SEQ/2)];
__device__ float2   g_rct[(size_t)SEQ*64];        // (cos, sin) per (t, d)

// ---------------------------------------------------------------------------
// helpers
// ---------------------------------------------------------------------------
__device__ __forceinline__ uint32_t f32_to_tf32(float f) {
    uint32_t r;
    asm("cvt.rna.tf32.f32 %0, %1;" : "=r"(r) : "f"(f));
    return r;
}

__device__ __forceinline__ void mma_tf32_16x8x8(float c[4], const uint32_t a[4], uint32_t b0, uint32_t b1) {
    asm volatile(
        "mma.sync.aligned.m16n8k8.row.col.f32.tf32.tf32.f32 "
        "{%0,%1,%2,%3}, {%4,%5,%6,%7}, {%8,%9}, {%0,%1,%2,%3};"
        : "+f"(c[0]), "+f"(c[1]), "+f"(c[2]), "+f"(c[3])
        : "r"(a[0]), "r"(a[1]), "r"(a[2]), "r"(a[3]), "r"(b0), "r"(b1));
}

__device__ __forceinline__ void mma_bf16_16x8x16(float c[4], const uint32_t a[4], uint32_t b0, uint32_t b1) {
    asm volatile(
        "mma.sync.aligned.m16n8k16.row.col.f32.bf16.bf16.f32 "
        "{%0,%1,%2,%3}, {%4,%5,%6,%7}, {%8,%9}, {%0,%1,%2,%3};"
        : "+f"(c[0]), "+f"(c[1]), "+f"(c[2]), "+f"(c[3])
        : "r"(a[0]), "r"(a[1]), "r"(a[2]), "r"(a[3]), "r"(b0), "r"(b1));
}

__device__ __forceinline__ uint32_t pack_bf2(float x, float y) {
    __nv_bfloat162 h = __float22bfloat162_rn(make_float2(x, y));
    return *(uint32_t*)&h;
}
__device__ __forceinline__ float bf2_lo_f32(uint32_t w) { return __uint_as_float(w << 16); }
__device__ __forceinline__ float bf2_hi_f32(uint32_t w) { return __uint_as_float(w & 0xffff0000u); }
__device__ __forceinline__ void split_bf2(float x, float y, uint32_t& hi, uint32_t& lo) {
    hi = pack_bf2(x, y);
    lo = pack_bf2(x - bf2_lo_f32(hi), y - bf2_hi_f32(hi));
}

__device__ __forceinline__ void cp16(void* dst, const void* src) {
    uint32_t s = (uint32_t)__cvta_generic_to_shared(dst);
    asm volatile("cp.async.cg.shared.global [%0], [%1], 16;" :: "r"(s), "l"(src));
}
__device__ __forceinline__ void cp_commit() { asm volatile("cp.async.commit_group;"); }
template<int N> __device__ __forceinline__ void cp_wait() { asm volatile("cp.async.wait_group %0;" :: "n"(N)); }

// ---------------------------------------------------------------------------
// Convert + permute x / weights to tf32 fragment layout (unchanged)
// ---------------------------------------------------------------------------
#define XCHUNKS ((size_t)(NROWS/16)*KBLKS*32)   // 2^21
#define WCHUNKS ((size_t)NB2T*KBLKS*32)         // 2^20

__global__ void cvt_perm_kernel(const float* __restrict__ x,
                                const float* __restrict__ Wq,
                                const float* __restrict__ Wk,
                                const float* __restrict__ Wv,
                                const float* __restrict__ Wo)
{
    size_t idx = (size_t)blockIdx.x * 256 + threadIdx.x;
    const int lane = (int)(idx & 31);
    const int g = lane >> 2, tg = lane & 3;
    uint4 o;
    if (idx < XCHUNKS) {
        int kb = (int)((idx >> 5) & (KBLKS - 1));
        int mb = (int)(idx >> 13);
        const float* s = x + (size_t)(mb * 16 + g) * DMODEL + kb * 8 + tg;
        o.x = f32_to_tf32(s[0]);
        o.y = f32_to_tf32(s[8 * DMODEL]);
        o.z = f32_to_tf32(s[4]);
        o.w = f32_to_tf32(s[8 * DMODEL + 4]);
        ((uint4*)g_xp)[idx] = o;
    } else {
        size_t j = idx - XCHUNKS;
        int wsel = (int)(j >> 20);
        size_t o2 = j & ((((size_t)1) << 20) - 1);
        int kb = (int)((o2 >> 5) & (KBLKS - 1));
        int nb2 = (int)(o2 >> 13);
        const float* W = (wsel == 0) ? Wq : (wsel == 1) ? Wk : (wsel == 2) ? Wv : Wo;
        const float* s = W + (size_t)(nb2 * 16 + g) * DMODEL + kb * 8 + tg;
        o.x = f32_to_tf32(s[0]);
        o.y = f32_to_tf32(s[4]);
        o.z = f32_to_tf32(s[8 * DMODEL]);
        o.w = f32_to_tf32(s[8 * DMODEL + 4]);
        ((uint4*)g_wp)[(size_t)wsel * WCHUNKS + o2] = o;
    }
}

// ---------------------------------------------------------------------------
// tf32 NT GEMM on fragment-permuted operands (unchanged from R9)
// ---------------------------------------------------------------------------
#define ABYTES (8*4*32*16)     // 16384
#define BBYTES (8*4*32*16)     // 16384
#define STGB   (ABYTES + BBYTES)   // 32768
#define NSTG 2
#define GEMM_SMEM (NSTG * STGB)    // 65536

template<int MODE>
__global__ void __launch_bounds__(128, 3) gemm_perm_kernel(
    const float* __restrict__ bias, float* __restrict__ Cout)
{
    extern __shared__ char sh[];

    const int tid  = threadIdx.x;
    const int lane = tid & 31;
    const int wrp  = tid >> 5;
    const int g    = lane >> 2;
    const int tg   = lane & 3;
    const int rh   = wrp >> 1;
    const int cw   = wrp & 1;

    const int rowBase = blockIdx.y * 128;
    const int colBase = blockIdx.x * 128;
    const int mb0  = blockIdx.y * 8;
    const int nb20 = blockIdx.x * 8;

    const uint32_t* Ag = (MODE == 0) ? g_xp : g_cp;
    const uint32_t* Bg = g_wp + (size_t)((MODE == 0) ? blockIdx.z : 3) * WSZ;
    float* dstQKV = nullptr;
    if (MODE == 0)
        dstQKV = (blockIdx.z == 0) ? g_q : (blockIdx.z == 1 ? g_k : g_v);

    auto issue = [&](int kt, int s) {
        char* st = sh + s * STGB;
        const int kb0 = kt * 4;
        #pragma unroll
        for (int p = 0; p < 8; p++) {
            int c = tid + p * 128;
            int mbL = c >> 7, kbL = (c >> 5) & 3, ln = c & 31;
            const uint32_t* gsrc = Ag + (((size_t)(mb0 + mbL) * KBLKS + kb0 + kbL) * 32 + ln) * 4;
            cp16(st + c * 16, gsrc);
        }
        #pragma unroll
        for (int p = 0; p < 8; p++) {
            int c = tid + p * 128;
            int nbL = c >> 7, kbL = (c >> 5) & 3, ln = c & 31;
            const uint32_t* gsrc = Bg + (((size_t)(nb20 + nbL) * KBLKS + kb0 + kbL) * 32 + ln) * 4;
            cp16(st + ABYTES + c * 16, gsrc);
        }
    };

    float acc[4][8][4];
    #pragma unroll
    for (int i = 0; i < 4; i++)
        #pragma unroll
        for (int j = 0; j < 8; j++)
            #pragma unroll
            for (int c = 0; c < 4; c++) acc[i][j][c] = 0.f;

    issue(0, 0); cp_commit();
    issue(1, 1); cp_commit();

    const int NKT = DMODEL / 32;
    for (int kt = 0; kt < NKT; kt++) {
        cp_wait<1>();
        __syncthreads();

        const char* st = sh + (kt & 1) * STGB;
        const uint4* As4 = (const uint4*)st;
        const uint4* Bs4 = (const uint4*)(st + ABYTES);

        #pragma unroll
        for (int kk = 0; kk < 4; kk++) {
            uint4 af[4];
            #pragma unroll
            for (int i = 0; i < 4; i++)
                af[i] = As4[((rh * 4 + i) * 4 + kk) * 32 + lane];
            #pragma unroll
            for (int j2 = 0; j2 < 4; j2++) {
                uint4 bv = Bs4[((cw * 4 + j2) * 4 + kk) * 32 + lane];
                #pragma unroll
                for (int i = 0; i < 4; i++) {
                    mma_tf32_16x8x8(acc[i][2*j2  ], (const uint32_t*)&af[i], bv.x, bv.y);
                    mma_tf32_16x8x8(acc[i][2*j2+1], (const uint32_t*)&af[i], bv.z, bv.w);
                }
            }
        }

        __syncthreads();
        if (kt + 2 < NKT) issue(kt + 2, kt & 1);
        cp_commit();
    }

    if (MODE == 0) {
        #pragma unroll
        for (int i = 0; i < 4; i++) {
            #pragma unroll
            for (int cc = 0; cc < 2; cc++) {
                int m = rowBase + rh * 64 + i * 16 + g + cc * 8;
                int b = m >> 11;
                int t = m & (SEQ - 1);
                size_t rowoff = ((size_t)(b * NHEADS) * SEQ + t) << 7;
                #pragma unroll
                for (int j = 0; j < 8; j++) {
                    int n0 = colBase + cw * 64 + j * 8 + tg * 2;
                    int h  = n0 >> 7;
                    int dh = n0 & (HDIM - 1);
                    float* dst = dstQKV + rowoff + (((size_t)h * SEQ) << 7) + dh;
                    dst[0] = acc[i][j][cc * 2 + 0];
                    dst[1] = acc[i][j][cc * 2 + 1];
                }
            }
        }
    } else {
        #pragma unroll
        for (int i = 0; i < 4; i++) {
            #pragma unroll
            for (int cc = 0; cc < 2; cc++) {
                int m = rowBase + rh * 64 + i * 16 + g + cc * 8;
                #pragma unroll
                for (int j = 0; j < 8; j++) {
                    int n0 = colBase + cw * 64 + j * 8 + tg * 2;
                    float2 v;
                    v.x = acc[i][j][cc * 2 + 0] + bias[n0];
                    v.y = acc[i][j][cc * 2 + 1] + bias[n0 + 1];
                    *(float2*)(Cout + (size_t)m * DMODEL + n0) = v;
                }
            }
        }
    }
}

// ---------------------------------------------------------------------------
// RoPE cos/sin table
// ---------------------------------------------------------------------------
__global__ void rope_table_kernel(const float* __restrict__ theta)
{
    int t = blockIdx.x;
    int d = threadIdx.x;   // 0..63
    float s, c;
    sincosf((float)t * theta[d], &s, &c);
    g_rct[(size_t)t * 64 + d] = make_float2(c, s);
}

// ---------------------------------------------------------------------------
// RoPE -> pre-split bf16 q/k words, written FRAGMENT-PERMUTED (unchanged).
// ---------------------------------------------------------------------------
__global__ void rope_split_kernel()
{
    const int j  = threadIdx.x;                    // 0..63
    const int t  = blockIdx.x * 4 + threadIdx.y;
    const int bh = blockIdx.y;
    const bool isK = blockIdx.z != 0;
    const int jj = j & 31;

    const float* row = (isK ? g_k : g_q) + ((size_t)bh * SEQ + t) * HDIM;
    float4 v = *(const float4*)(row + 4 * jj);
    float4 tc = *(const float4*)&g_rct[(size_t)t * 64 + 2 * jj];   // (c0,s0,c1,s1)

    float o0, o1;
    if (j < 32) { o0 = v.x * tc.x - v.y * tc.y;  o1 = v.z * tc.z - v.w * tc.w; }
    else        { o0 = v.x * tc.y + v.y * tc.x;  o1 = v.z * tc.w + v.w * tc.z; }

    uint32_t hi, lo;
    split_bf2(o0, o1, hi, lo);

    const int r16 = t & 15;
    const int lane2 = (r16 & 7) * 4 + (j & 3);
    const int wq = (r16 >> 3) | (((j >> 2) & 1) << 1);
    const int wk = ((j >> 2) & 1) | ((r16 >> 3) << 1);
    const int w = isK ? wk : wq;
    size_t word = (((size_t)(bh * 128 + (t >> 4)) * 8 + (j >> 3)) * 32 + lane2) * 4 + w;
    (isK ? g_kh : g_qh)[word] = hi;
    (isK ? g_kl : g_ql)[word] = lo;
}

// ---------------------------------------------------------------------------
// V prep: transpose + split V, written B-perm over d (unchanged).
// ---------------------------------------------------------------------------
__global__ void __launch_bounds__(256) v_prep_kernel()
{
    __shared__ float sm[128 * 37];
    const int tid = threadIdx.x;
    const int t0 = blockIdx.x * 128;
    const int d0 = blockIdx.y * 32;
    const int bh = blockIdx.z;
    const float* src = g_v + ((size_t)bh * SEQ + t0) * HDIM + d0;

    #pragma unroll
    for (int p = 0; p < 4; p++) {
        int c = tid + p * 256;
        int t = c >> 3;
        int q = (c & 7) * 4;
        float4 v = *(const float4*)(src + (size_t)t * HDIM + q);
        float* d = sm + t * 37 + q;
        d[0] = v.x; d[1] = v.y; d[2] = v.z; d[3] = v.w;
    }
    __syncthreads();

    #pragma unroll
    for (int p = 0; p < 8; p++) {
        int wi = tid + p * 256;
        int dl = wi >> 6;                 // 0..31 local d
        int tpl = wi & 63;                // 0..63 local tpair
        uint32_t hi, lo;
        split_bf2(sm[(2*tpl) * 37 + dl], sm[(2*tpl + 1) * 37 + dl], hi, lo);

        int dg = d0 + dl;
        int tpg = t0 / 2 + tpl;
        int lane2 = (dg & 7) * 4 + (tpg & 3);
        int w = ((tpg >> 2) & 1) | (((dg & 15) >> 3) << 1);
        size_t word = (((size_t)(bh * 8 + (dg >> 4)) * 128 + (tpg >> 3)) * 32 + lane2) * 4 + w;
        g_vth[word] = hi;
        g_vtl[word] = lo;
    }
}

// ---------------------------------------------------------------------------
// Tensor-core flash attention (bf16x3), causal, fragment-permuted operands.
// NEW (R13): Q fragments in REGISTERS (loaded once via LDG.128), 3-stage KV
// ring (96 KB), ONE barrier per k-tile. 128 threads, 2 CTAs/SM.
// stage (words): Khi[2048] Klo[2048] Vhi[2048] Vlo[2048] = 8192
// ---------------------------------------------------------------------------
#define AKHI 0
#define AKLO 2048
#define AVHI 4096
#define AVLO 6144
#define ASTSZ 8192
#define ATTN_SMEM_BYTES (3 * ASTSZ * 4)   // 98304

__global__ void __launch_bounds__(128, 2) attn_bf16_kernel()
{
    extern __shared__ uint32_t sm[];

    const int tid  = threadIdx.x;
    const int lane = tid & 31;
    const int wrp  = tid >> 5;      // 0..3
    const int g    = lane >> 2;
    const int tg   = lane & 3;
    const int wr   = wrp * 16;

    const int qt = gridDim.x - 1 - blockIdx.x;   // big tiles first
    const int bh = blockIdx.y;
    const int qs = qt * 64;
    const float scale = 0.08838834764831845f;
    const int ktiles = 2 * qt + 2;               // 32-wide k tiles

    const uint4* Qg4  = (const uint4*)g_qh + (size_t)(bh * 128) * 8 * 32;
    const uint4* QgL4 = (const uint4*)g_ql + (size_t)(bh * 128) * 8 * 32;
    const uint4* Kg4  = (const uint4*)g_kh + (size_t)(bh * 128) * 8 * 32;
    const uint4* KgL4 = (const uint4*)g_kl + (size_t)(bh * 128) * 8 * 32;
    const uint4* Vg4  = (const uint4*)g_vth + (size_t)(bh * 8) * 128 * 32;
    const uint4* VgL4 = (const uint4*)g_vtl + (size_t)(bh * 8) * 128 * 32;

    // Q fragments: each warp loads its own 16 rows once (registers)
    uint4 qh4[8], ql4[8];
    #pragma unroll
    for (int kk = 0; kk < 8; kk++) {
        qh4[kk] = Qg4[((size_t)(qt * 4 + wrp) * 8 + kk) * 32 + lane];
        ql4[kk] = QgL4[((size_t)(qt * 4 + wrp) * 8 + kk) * 32 + lane];
    }

    auto issueKV = [&](int kt) {
        if (kt >= ktiles) return;
        uint32_t* st = sm + (kt % 3) * ASTSZ;
        #pragma unroll
        for (int p = 0; p < 4; p++) {                  // K: 512 chunks
            int c = tid + p * 128;
            int nbL = c >> 8, kbL = (c >> 5) & 7, ln = c & 31;
            cp16(st + AKHI + c * 4, Kg4 + ((size_t)(kt * 2 + nbL) * 8 + kbL) * 32 + ln);
            cp16(st + AKLO + c * 4, KgL4 + ((size_t)(kt * 2 + nbL) * 8 + kbL) * 32 + ln);
        }
        #pragma unroll
        for (int p = 0; p < 4; p++) {                  // V: 512 chunks
            int c = tid + p * 128;
            int dnbL = c >> 6, kbL = (c >> 5) & 1, ln = c & 31;
            cp16(st + AVHI + c * 4, Vg4 + ((size_t)dnbL * 128 + kt * 2 + kbL) * 32 + ln);
            cp16(st + AVLO + c * 4, VgL4 + ((size_t)dnbL * 128 + kt * 2 + kbL) * 32 + ln);
        }
    };

    issueKV(0); cp_commit();
    issueKV(1); cp_commit();

    float o[16][4];
    #pragma unroll
    for (int j = 0; j < 16; j++)
        #pragma unroll
        for (int c = 0; c < 4; c++) o[j][c] = 0.f;
    float l0s = 0.f, l1s = 0.f;

    for (int kt = 0; kt < ktiles; kt++) {
        const int ks = kt * 32;
        cp_wait<1>();
        __syncthreads();                 // tile kt ready; all warps done with kt-1
        issueKV(kt + 2);                 // stage (kt+2)%3 == stage of kt-1: safe
        cp_commit();

        const uint4* Kh4 = (const uint4*)(sm + (kt % 3) * ASTSZ + AKHI);
        const uint4* Kl4 = (const uint4*)(sm + (kt % 3) * ASTSZ + AKLO);
        const uint4* Vh4 = (const uint4*)(sm + (kt % 3) * ASTSZ + AVHI);
        const uint4* Vl4 = (const uint4*)(sm + (kt % 3) * ASTSZ + AVLO);

        float sc[4][4];
        #pragma unroll
        for (int j = 0; j < 4; j++)
            #pragma unroll
            for (int c = 0; c < 4; c++) sc[j][c] = 0.f;

        #pragma unroll
        for (int kk = 0; kk < 8; kk++) {
            const uint32_t* ah = (const uint32_t*)&qh4[kk];
            const uint32_t* al = (const uint32_t*)&ql4[kk];
            #pragma unroll
            for (int nb = 0; nb < 2; nb++) {
                uint4 bh4 = Kh4[(nb * 8 + kk) * 32 + lane];
                uint4 bl4 = Kl4[(nb * 8 + kk) * 32 + lane];
                mma_bf16_16x8x16(sc[2*nb  ], ah, bh4.x, bh4.y);
                mma_bf16_16x8x16(sc[2*nb  ], ah, bl4.x, bl4.y);
                mma_bf16_16x8x16(sc[2*nb  ], al, bh4.x, bh4.y);
                mma_bf16_16x8x16(sc[2*nb+1], ah, bh4.z, bh4.w);
                mma_bf16_16x8x16(sc[2*nb+1], ah, bl4.z, bl4.w);
                mma_bf16_16x8x16(sc[2*nb+1], al, bh4.z, bh4.w);
            }
        }

        const int r0 = qs + wr + g;
        const int r1 = r0 + 8;
        const bool part = (ks + 31 > qs + wr);
        #pragma unroll
        for (int j = 0; j < 4; j++) {
            int cb = ks + j * 8 + 2 * tg;
            sc[j][0] = (part && cb     > r0) ? -1e30f : sc[j][0] * scale;
            sc[j][1] = (part && cb + 1 > r0) ? -1e30f : sc[j][1] * scale;
            sc[j][2] = (part && cb     > r1) ? -1e30f : sc[j][2] * scale;
            sc[j][3] = (part && cb + 1 > r1) ? -1e30f : sc[j][3] * scale;
        }

        #pragma unroll
        for (int j = 0; j < 4; j++) {
            sc[j][0] = __expf(sc[j][0]); l0s += sc[j][0];
            sc[j][1] = __expf(sc[j][1]); l0s += sc[j][1];
            sc[j][2] = __expf(sc[j][2]); l1s += sc[j][2];
            sc[j][3] = __expf(sc[j][3]); l1s += sc[j][3];
        }

        #pragma unroll
        for (int k2 = 0; k2 < 2; k2++) {
            uint32_t ah[4], al[4];
            split_bf2(sc[2*k2  ][0], sc[2*k2  ][1], ah[0], al[0]);
            split_bf2(sc[2*k2  ][2], sc[2*k2  ][3], ah[1], al[1]);
            split_bf2(sc[2*k2+1][0], sc[2*k2+1][1], ah[2], al[2]);
            split_bf2(sc[2*k2+1][2], sc[2*k2+1][3], ah[3], al[3]);
            #pragma unroll
            for (int dnb = 0; dnb < 8; dnb++) {
                uint4 vh4 = Vh4[(dnb * 2 + k2) * 32 + lane];
                uint4 vl4 = Vl4[(dnb * 2 + k2) * 32 + lane];
                mma_bf16_16x8x16(o[2*dnb  ], ah, vh4.x, vh4.y);
                mma_bf16_16x8x16(o[2*dnb  ], ah, vl4.x, vl4.y);
                mma_bf16_16x8x16(o[2*dnb  ], al, vh4.x, vh4.y);
                mma_bf16_16x8x16(o[2*dnb+1], ah, vh4.z, vh4.w);
                mma_bf16_16x8x16(o[2*dnb+1], ah, vl4.z, vl4.w);
                mma_bf16_16x8x16(o[2*dnb+1], al, vh4.z, vh4.w);
            }
        }
    }

    // reduce l over the tg quad (once)
    l0s += __shfl_xor_sync(0xffffffff, l0s, 1);
    l0s += __shfl_xor_sync(0xffffffff, l0s, 2);
    l1s += __shfl_xor_sync(0xffffffff, l1s, 1);
    l1s += __shfl_xor_sync(0xffffffff, l1s, 2);

    // ---- epilogue: ctx -> g_cp (tf32 bits, A-fragment-permuted) ----
    const float inv0 = 1.f / l0s;
    const float inv1 = 1.f / l1s;
    const int b = bh >> 4;
    const int h = bh & 15;
    const int m_blk = (b * SEQ + qs + wr) >> 4;
    const int lane0 = 4 * g + (tg & 1) * 2;
    const int w0 = (tg >> 1) * 2;
    #pragma unroll
    for (int jd = 0; jd < 16; jd++) {
        int kblk = h * 16 + jd;
        uint32_t* p = g_cp + (((size_t)m_blk * KBLKS + kblk) * 32 + lane0) * 4 + w0;
        *(uint2*)p       = make_uint2(f32_to_tf32(o[jd][0] * inv0), f32_to_tf32(o[jd][2] * inv1));
        *(uint2*)(p + 4) = make_uint2(f32_to_tf32(o[jd][1] * inv0), f32_to_tf32(o[jd][3] * inv1));
    }
}

// ---------------------------------------------------------------------------
extern "C" void kernel_launch(void* const* d_in, const int* in_sizes, int n_in,
                              void* d_out, int out_size)
{
    const float* x     = (const float*)d_in[0];
    const float* Wq    = (const float*)d_in[1];
    const float* Wk    = (const float*)d_in[2];
    const float* Wv    = (const float*)d_in[3];
    const float* Wo    = (const float*)d_in[4];
    const float* bo    = (const float*)d_in[5];
    const float* theta = (const float*)d_in[6];
    float* out = (float*)d_out;

    // 0. Convert + permute x and weights; build rope cos/sin table
    const size_t total_chunks = XCHUNKS + 4 * WCHUNKS;
    cvt_perm_kernel<<<(unsigned)(total_chunks / 256), 256>>>(x, Wq, Wk, Wv, Wo);
    rope_table_kernel<<<SEQ, 64>>>(theta);

    // 1. QKV projections (128x128 tiles, 3 CTAs/SM), scatter to [b,h,t,dh]
    cudaFuncSetAttribute(gemm_perm_kernel<0>, cudaFuncAttributeMaxDynamicSharedMemorySize, GEMM_SMEM);
    gemm_perm_kernel<0><<<dim3(DMODEL/128, NROWS/128, 3), 128, GEMM_SMEM>>>(nullptr, nullptr);

    // 2. RoPE -> fragment-permuted bf16 q/k;  V transpose+split (B-perm)
    rope_split_kernel<<<dim3(SEQ/4, BSZ*NHEADS, 2), dim3(64, 4)>>>();
    v_prep_kernel<<<dim3(SEQ/128, HDIM/32, BSZ*NHEADS), 256>>>();

    // 3. Causal flash attention (bf16x3, Q in regs, 3-stage KV, 2 CTAs/SM)
    cudaFuncSetAttribute(attn_bf16_kernel, cudaFuncAttributeMaxDynamicSharedMemorySize, ATTN_SMEM_BYTES);
    attn_bf16_kernel<<<dim3(SEQ/64, BSZ*NHEADS), 128, ATTN_SMEM_BYTES>>>();

    // 4. Output projection + bias
    cudaFuncSetAttribute(gemm_perm_kernel<1>, cudaFuncAttributeMaxDynamicSharedMemorySize, GEMM_SMEM);
    gemm_perm_kernel<1><<<dim3(DMODEL/128, NROWS/128, 1), 128, GEMM_SMEM>>>(bo, out);
}

// round 14
// speedup vs baseline: 1.5313x; 1.5313x over previous
#include <cuda_runtime.h>
#include <cuda_bf16.h>
#include <math.h>
#include <stdint.h>

#define BSZ 2
#define SEQ 2048
#define DMODEL 2048
#define NHEADS 16
#define HDIM 128
#define NROWS (BSZ*SEQ)     // 4096
#define WSZ (DMODEL*DMODEL)
#define KBLKS (DMODEL/8)    // 256 k8-blocks per row
#define NB2T (DMODEL/16)    // 128 n16-blocks

// Scratch (allocation-free rule: __device__ globals)
__device__ float    g_q[BSZ*NHEADS*SEQ*HDIM];
__device__ float    g_k[BSZ*NHEADS*SEQ*HDIM];
__device__ float    g_v[BSZ*NHEADS*SEQ*HDIM];
__device__ uint32_t g_xp[(size_t)NROWS*DMODEL];   // x, tf32 bits, A-fragment-permuted
__device__ uint32_t g_wp[(size_t)4*WSZ];          // Wq,Wk,Wv,Wo tf32 bits, B-fragment-permuted
__device__ uint32_t g_cp[(size_t)NROWS*DMODEL];   // ctx, tf32 bits, A-fragment-permuted
// attention operands, pre-split bf16 hi/lo packed words, FRAGMENT-PERMUTED:
//   q: A-perm  [bh][mb16][kb8][lane][4w]
//   k: B-perm  [bh][nb16][kb8][lane][4w]
//   v: B-perm over d, k-dim = tpairs  [bh][dnb16][kb8][lane][4w]
__device__ uint32_t g_qh[(size_t)BSZ*NHEADS*SEQ*64];
__device__ uint32_t g_ql[(size_t)BSZ*NHEADS*SEQ*64];
__device__ uint32_t g_kh[(size_t)BSZ*NHEADS*SEQ*64];
__device__ uint32_t g_kl[(size_t)BSZ*NHEADS*SEQ*64];
__device__ uint32_t g_vth[(size_t)BSZ*NHEADS*HDIM*(SEQ/2)];
__device__ uint32_t g_vtl[(size_t)BSZ*NHEADS*HDIM*(SEQ/2)];
__device__ float2   g_rct[(size_t)SEQ*64];        // (cos, sin) per (t, d)

// ---------------------------------------------------------------------------
// helpers
// ---------------------------------------------------------------------------
__device__ __forceinline__ uint32_t f32_to_tf32(float f) {
    uint32_t r;
    asm("cvt.rna.tf32.f32 %0, %1;" : "=r"(r) : "f"(f));
    return r;
}

__device__ __forceinline__ void mma_tf32_16x8x8(float c[4], const uint32_t a[4], uint32_t b0, uint32_t b1) {
    asm volatile(
        "mma.sync.aligned.m16n8k8.row.col.f32.tf32.tf32.f32 "
        "{%0,%1,%2,%3}, {%4,%5,%6,%7}, {%8,%9}, {%0,%1,%2,%3};"
        : "+f"(c[0]), "+f"(c[1]), "+f"(c[2]), "+f"(c[3])
        : "r"(a[0]), "r"(a[1]), "r"(a[2]), "r"(a[3]), "r"(b0), "r"(b1));
}

__device__ __forceinline__ void mma_bf16_16x8x16(float c[4], const uint32_t a[4], uint32_t b0, uint32_t b1) {
    asm volatile(
        "mma.sync.aligned.m16n8k16.row.col.f32.bf16.bf16.f32 "
        "{%0,%1,%2,%3}, {%4,%5,%6,%7}, {%8,%9}, {%0,%1,%2,%3};"
        : "+f"(c[0]), "+f"(c[1]), "+f"(c[2]), "+f"(c[3])
        : "r"(a[0]), "r"(a[1]), "r"(a[2]), "r"(a[3]), "r"(b0), "r"(b1));
}

__device__ __forceinline__ uint32_t pack_bf2(float x, float y) {
    __nv_bfloat162 h = __float22bfloat162_rn(make_float2(x, y));
    return *(uint32_t*)&h;
}
__device__ __forceinline__ float bf2_lo_f32(uint32_t w) { return __uint_as_float(w << 16); }
__device__ __forceinline__ float bf2_hi_f32(uint32_t w) { return __uint_as_float(w & 0xffff0000u); }
__device__ __forceinline__ void split_bf2(float x, float y, uint32_t& hi, uint32_t& lo) {
    hi = pack_bf2(x, y);
    lo = pack_bf2(x - bf2_lo_f32(hi), y - bf2_hi_f32(hi));
}

__device__ __forceinline__ void cp16(void* dst, const void* src) {
    uint32_t s = (uint32_t)__cvta_generic_to_shared(dst);
    asm volatile("cp.async.cg.shared.global [%0], [%1], 16;" :: "r"(s), "l"(src));
}
__device__ __forceinline__ void cp_commit() { asm volatile("cp.async.commit_group;"); }
template<int N> __device__ __forceinline__ void cp_wait() { asm volatile("cp.async.wait_group %0;" :: "n"(N)); }

// ---------------------------------------------------------------------------
// Convert + permute x / weights to tf32 fragment layout (unchanged)
// ---------------------------------------------------------------------------
#define XCHUNKS ((size_t)(NROWS/16)*KBLKS*32)   // 2^21
#define WCHUNKS ((size_t)NB2T*KBLKS*32)         // 2^20

__global__ void cvt_perm_kernel(const float* __restrict__ x,
                                const float* __restrict__ Wq,
                                const float* __restrict__ Wk,
                                const float* __restrict__ Wv,
                                const float* __restrict__ Wo)
{
    size_t idx = (size_t)blockIdx.x * 256 + threadIdx.x;
    const int lane = (int)(idx & 31);
    const int g = lane >> 2, tg = lane & 3;
    uint4 o;
    if (idx < XCHUNKS) {
        int kb = (int)((idx >> 5) & (KBLKS - 1));
        int mb = (int)(idx >> 13);
        const float* s = x + (size_t)(mb * 16 + g) * DMODEL + kb * 8 + tg;
        o.x = f32_to_tf32(s[0]);
        o.y = f32_to_tf32(s[8 * DMODEL]);
        o.z = f32_to_tf32(s[4]);
        o.w = f32_to_tf32(s[8 * DMODEL + 4]);
        ((uint4*)g_xp)[idx] = o;
    } else {
        size_t j = idx - XCHUNKS;
        int wsel = (int)(j >> 20);
        size_t o2 = j & ((((size_t)1) << 20) - 1);
        int kb = (int)((o2 >> 5) & (KBLKS - 1));
        int nb2 = (int)(o2 >> 13);
        const float* W = (wsel == 0) ? Wq : (wsel == 1) ? Wk : (wsel == 2) ? Wv : Wo;
        const float* s = W + (size_t)(nb2 * 16 + g) * DMODEL + kb * 8 + tg;
        o.x = f32_to_tf32(s[0]);
        o.y = f32_to_tf32(s[4]);
        o.z = f32_to_tf32(s[8 * DMODEL]);
        o.w = f32_to_tf32(s[8 * DMODEL + 4]);
        ((uint4*)g_wp)[(size_t)wsel * WCHUNKS + o2] = o;
    }
}

// ---------------------------------------------------------------------------
// tf32 NT GEMM on fragment-permuted operands (unchanged from R9)
// ---------------------------------------------------------------------------
#define ABYTES (8*4*32*16)     // 16384
#define BBYTES (8*4*32*16)     // 16384
#define STGB   (ABYTES + BBYTES)   // 32768
#define NSTG 2
#define GEMM_SMEM (NSTG * STGB)    // 65536

template<int MODE>
__global__ void __launch_bounds__(128, 3) gemm_perm_kernel(
    const float* __restrict__ bias, float* __restrict__ Cout)
{
    extern __shared__ char sh[];

    const int tid  = threadIdx.x;
    const int lane = tid & 31;
    const int wrp  = tid >> 5;
    const int g    = lane >> 2;
    const int tg   = lane & 3;
    const int rh   = wrp >> 1;
    const int cw   = wrp & 1;

    const int rowBase = blockIdx.y * 128;
    const int colBase = blockIdx.x * 128;
    const int mb0  = blockIdx.y * 8;
    const int nb20 = blockIdx.x * 8;

    const uint32_t* Ag = (MODE == 0) ? g_xp : g_cp;
    const uint32_t* Bg = g_wp + (size_t)((MODE == 0) ? blockIdx.z : 3) * WSZ;
    float* dstQKV = nullptr;
    if (MODE == 0)
        dstQKV = (blockIdx.z == 0) ? g_q : (blockIdx.z == 1 ? g_k : g_v);

    auto issue = [&](int kt, int s) {
        char* st = sh + s * STGB;
        const int kb0 = kt * 4;
        #pragma unroll
        for (int p = 0; p < 8; p++) {
            int c = tid + p * 128;
            int mbL = c >> 7, kbL = (c >> 5) & 3, ln = c & 31;
            const uint32_t* gsrc = Ag + (((size_t)(mb0 + mbL) * KBLKS + kb0 + kbL) * 32 + ln) * 4;
            cp16(st + c * 16, gsrc);
        }
        #pragma unroll
        for (int p = 0; p < 8; p++) {
            int c = tid + p * 128;
            int nbL = c >> 7, kbL = (c >> 5) & 3, ln = c & 31;
            const uint32_t* gsrc = Bg + (((size_t)(nb20 + nbL) * KBLKS + kb0 + kbL) * 32 + ln) * 4;
            cp16(st + ABYTES + c * 16, gsrc);
        }
    };

    float acc[4][8][4];
    #pragma unroll
    for (int i = 0; i < 4; i++)
        #pragma unroll
        for (int j = 0; j < 8; j++)
            #pragma unroll
            for (int c = 0; c < 4; c++) acc[i][j][c] = 0.f;

    issue(0, 0); cp_commit();
    issue(1, 1); cp_commit();

    const int NKT = DMODEL / 32;
    for (int kt = 0; kt < NKT; kt++) {
        cp_wait<1>();
        __syncthreads();

        const char* st = sh + (kt & 1) * STGB;
        const uint4* As4 = (const uint4*)st;
        const uint4* Bs4 = (const uint4*)(st + ABYTES);

        #pragma unroll
        for (int kk = 0; kk < 4; kk++) {
            uint4 af[4];
            #pragma unroll
            for (int i = 0; i < 4; i++)
                af[i] = As4[((rh * 4 + i) * 4 + kk) * 32 + lane];
            #pragma unroll
            for (int j2 = 0; j2 < 4; j2++) {
                uint4 bv = Bs4[((cw * 4 + j2) * 4 + kk) * 32 + lane];
                #pragma unroll
                for (int i = 0; i < 4; i++) {
                    mma_tf32_16x8x8(acc[i][2*j2  ], (const uint32_t*)&af[i], bv.x, bv.y);
                    mma_tf32_16x8x8(acc[i][2*j2+1], (const uint32_t*)&af[i], bv.z, bv.w);
                }
            }
        }

        __syncthreads();
        if (kt + 2 < NKT) issue(kt + 2, kt & 1);
        cp_commit();
    }

    if (MODE == 0) {
        #pragma unroll
        for (int i = 0; i < 4; i++) {
            #pragma unroll
            for (int cc = 0; cc < 2; cc++) {
                int m = rowBase + rh * 64 + i * 16 + g + cc * 8;
                int b = m >> 11;
                int t = m & (SEQ - 1);
                size_t rowoff = ((size_t)(b * NHEADS) * SEQ + t) << 7;
                #pragma unroll
                for (int j = 0; j < 8; j++) {
                    int n0 = colBase + cw * 64 + j * 8 + tg * 2;
                    int h  = n0 >> 7;
                    int dh = n0 & (HDIM - 1);
                    float* dst = dstQKV + rowoff + (((size_t)h * SEQ) << 7) + dh;
                    dst[0] = acc[i][j][cc * 2 + 0];
                    dst[1] = acc[i][j][cc * 2 + 1];
                }
            }
        }
    } else {
        #pragma unroll
        for (int i = 0; i < 4; i++) {
            #pragma unroll
            for (int cc = 0; cc < 2; cc++) {
                int m = rowBase + rh * 64 + i * 16 + g + cc * 8;
                #pragma unroll
                for (int j = 0; j < 8; j++) {
                    int n0 = colBase + cw * 64 + j * 8 + tg * 2;
                    float2 v;
                    v.x = acc[i][j][cc * 2 + 0] + bias[n0];
                    v.y = acc[i][j][cc * 2 + 1] + bias[n0 + 1];
                    *(float2*)(Cout + (size_t)m * DMODEL + n0) = v;
                }
            }
        }
    }
}

// ---------------------------------------------------------------------------
// RoPE cos/sin table
// ---------------------------------------------------------------------------
__global__ void rope_table_kernel(const float* __restrict__ theta)
{
    int t = blockIdx.x;
    int d = threadIdx.x;   // 0..63
    float s, c;
    sincosf((float)t * theta[d], &s, &c);
    g_rct[(size_t)t * 64 + d] = make_float2(c, s);
}

// ---------------------------------------------------------------------------
// RoPE -> pre-split bf16 q/k words, written FRAGMENT-PERMUTED (unchanged).
// ---------------------------------------------------------------------------
__global__ void rope_split_kernel()
{
    const int j  = threadIdx.x;                    // 0..63
    const int t  = blockIdx.x * 4 + threadIdx.y;
    const int bh = blockIdx.y;
    const bool isK = blockIdx.z != 0;
    const int jj = j & 31;

    const float* row = (isK ? g_k : g_q) + ((size_t)bh * SEQ + t) * HDIM;
    float4 v = *(const float4*)(row + 4 * jj);
    float4 tc = *(const float4*)&g_rct[(size_t)t * 64 + 2 * jj];   // (c0,s0,c1,s1)

    float o0, o1;
    if (j < 32) { o0 = v.x * tc.x - v.y * tc.y;  o1 = v.z * tc.z - v.w * tc.w; }
    else        { o0 = v.x * tc.y + v.y * tc.x;  o1 = v.z * tc.w + v.w * tc.z; }

    uint32_t hi, lo;
    split_bf2(o0, o1, hi, lo);

    const int r16 = t & 15;
    const int lane2 = (r16 & 7) * 4 + (j & 3);
    const int wq = (r16 >> 3) | (((j >> 2) & 1) << 1);
    const int wk = ((j >> 2) & 1) | ((r16 >> 3) << 1);
    const int w = isK ? wk : wq;
    size_t word = (((size_t)(bh * 128 + (t >> 4)) * 8 + (j >> 3)) * 32 + lane2) * 4 + w;
    (isK ? g_kh : g_qh)[word] = hi;
    (isK ? g_kl : g_ql)[word] = lo;
}

// ---------------------------------------------------------------------------
// V prep: transpose + split V, written B-perm over d (unchanged).
// ---------------------------------------------------------------------------
__global__ void __launch_bounds__(256) v_prep_kernel()
{
    __shared__ float sm[128 * 37];
    const int tid = threadIdx.x;
    const int t0 = blockIdx.x * 128;
    const int d0 = blockIdx.y * 32;
    const int bh = blockIdx.z;
    const float* src = g_v + ((size_t)bh * SEQ + t0) * HDIM + d0;

    #pragma unroll
    for (int p = 0; p < 4; p++) {
        int c = tid + p * 256;
        int t = c >> 3;
        int q = (c & 7) * 4;
        float4 v = *(const float4*)(src + (size_t)t * HDIM + q);
        float* d = sm + t * 37 + q;
        d[0] = v.x; d[1] = v.y; d[2] = v.z; d[3] = v.w;
    }
    __syncthreads();

    #pragma unroll
    for (int p = 0; p < 8; p++) {
        int wi = tid + p * 256;
        int dl = wi >> 6;                 // 0..31 local d
        int tpl = wi & 63;                // 0..63 local tpair
        uint32_t hi, lo;
        split_bf2(sm[(2*tpl) * 37 + dl], sm[(2*tpl + 1) * 37 + dl], hi, lo);

        int dg = d0 + dl;
        int tpg = t0 / 2 + tpl;
        int lane2 = (dg & 7) * 4 + (tpg & 3);
        int w = ((tpg >> 2) & 1) | (((dg & 15) >> 3) << 1);
        size_t word = (((size_t)(bh * 8 + (dg >> 4)) * 128 + (tpg >> 3)) * 32 + lane2) * 4 + w;
        g_vth[word] = hi;
        g_vtl[word] = lo;
    }
}

// ---------------------------------------------------------------------------
// Tensor-core flash attention (bf16x3), causal, fragment-permuted operands.
// R12 proven skeleton (2-stage, 2-barrier, 2 CTAs/SM) with ONE safe change:
// Q-HI fragments live in registers (8 x uint4, loaded once via LDG.128);
// Q-LO stays in smem. ~222 regs, no spill risk.
// smem (words): Qlo[4096]; stage: Khi[2048] Klo[2048] Vhi[2048] Vlo[2048]
// ---------------------------------------------------------------------------
#define AQLO 0
#define AST0 4096
#define ASTSZ 8192
#define AKHI 0
#define AKLO 2048
#define AVHI 4096
#define AVLO 6144
#define ATTN_SMEM_BYTES ((AST0 + 2*ASTSZ) * 4)   // 81920

__global__ void __launch_bounds__(128, 2) attn_bf16_kernel()
{
    extern __shared__ uint32_t sm[];

    const int tid  = threadIdx.x;
    const int lane = tid & 31;
    const int wrp  = tid >> 5;      // 0..3
    const int g    = lane >> 2;
    const int tg   = lane & 3;
    const int wr   = wrp * 16;

    const int qt = gridDim.x - 1 - blockIdx.x;   // big tiles first
    const int bh = blockIdx.y;
    const int qs = qt * 64;
    const float scale = 0.08838834764831845f;
    const int ktiles = 2 * qt + 2;               // 32-wide k tiles

    const uint4* Qg4  = (const uint4*)g_qh + (size_t)(bh * 128) * 8 * 32;
    const uint4* QgL4 = (const uint4*)g_ql + (size_t)(bh * 128) * 8 * 32;
    const uint4* Kg4  = (const uint4*)g_kh + (size_t)(bh * 128) * 8 * 32;
    const uint4* KgL4 = (const uint4*)g_kl + (size_t)(bh * 128) * 8 * 32;
    const uint4* Vg4  = (const uint4*)g_vth + (size_t)(bh * 8) * 128 * 32;
    const uint4* VgL4 = (const uint4*)g_vtl + (size_t)(bh * 8) * 128 * 32;

    // Q-hi fragments: each warp loads its own 16 rows once into registers
    uint4 qh4[8];
    #pragma unroll
    for (int kk = 0; kk < 8; kk++)
        qh4[kk] = Qg4[((size_t)(qt * 4 + wrp) * 8 + kk) * 32 + lane];

    auto issueKV = [&](int kt) {
        if (kt >= ktiles) return;
        uint32_t* st = sm + AST0 + (kt & 1) * ASTSZ;
        #pragma unroll
        for (int p = 0; p < 4; p++) {                  // K: 512 chunks
            int c = tid + p * 128;
            int nbL = c >> 8, kbL = (c >> 5) & 7, ln = c & 31;
            cp16(st + AKHI + c * 4, Kg4 + ((size_t)(kt * 2 + nbL) * 8 + kbL) * 32 + ln);
            cp16(st + AKLO + c * 4, KgL4 + ((size_t)(kt * 2 + nbL) * 8 + kbL) * 32 + ln);
        }
        #pragma unroll
        for (int p = 0; p < 4; p++) {                  // V: 512 chunks
            int c = tid + p * 128;
            int dnbL = c >> 6, kbL = (c >> 5) & 1, ln = c & 31;
            cp16(st + AVHI + c * 4, Vg4 + ((size_t)dnbL * 128 + kt * 2 + kbL) * 32 + ln);
            cp16(st + AVLO + c * 4, VgL4 + ((size_t)dnbL * 128 + kt * 2 + kbL) * 32 + ln);
        }
    };

    // Q-lo load (once): 1024 chunks (4 mb x 8 kb x 32)
    #pragma unroll
    for (int p = 0; p < 8; p++) {
        int c = tid + p * 128;
        int mbL = c >> 8, kbL = (c >> 5) & 7, ln = c & 31;
        cp16(sm + AQLO + c * 4, QgL4 + ((size_t)(qt * 4 + mbL) * 8 + kbL) * 32 + ln);
    }
    issueKV(0); cp_commit();
    issueKV(1); cp_commit();

    float o[16][4];
    #pragma unroll
    for (int j = 0; j < 16; j++)
        #pragma unroll
        for (int c = 0; c < 4; c++) o[j][c] = 0.f;
    float l0s = 0.f, l1s = 0.f;

    for (int kt = 0; kt < ktiles; kt++) {
        const int ks = kt * 32;
        cp_wait<1>();
        __syncthreads();

        const uint4* Kh4 = (const uint4*)(sm + AST0 + (kt & 1) * ASTSZ + AKHI);
        const uint4* Kl4 = (const uint4*)(sm + AST0 + (kt & 1) * ASTSZ + AKLO);
        const uint4* Vh4 = (const uint4*)(sm + AST0 + (kt & 1) * ASTSZ + AVHI);
        const uint4* Vl4 = (const uint4*)(sm + AST0 + (kt & 1) * ASTSZ + AVLO);
        const uint4* Ql4 = (const uint4*)(sm + AQLO);

        float sc[4][4];
        #pragma unroll
        for (int j = 0; j < 4; j++)
            #pragma unroll
            for (int c = 0; c < 4; c++) sc[j][c] = 0.f;

        #pragma unroll
        for (int kk = 0; kk < 8; kk++) {
            uint4 al4 = Ql4[(wrp * 8 + kk) * 32 + lane];
            const uint32_t* ah = (const uint32_t*)&qh4[kk];
            const uint32_t* al = (const uint32_t*)&al4;
            #pragma unroll
            for (int nb = 0; nb < 2; nb++) {
                uint4 bh4 = Kh4[(nb * 8 + kk) * 32 + lane];
                uint4 bl4 = Kl4[(nb * 8 + kk) * 32 + lane];
                mma_bf16_16x8x16(sc[2*nb  ], ah, bh4.x, bh4.y);
                mma_bf16_16x8x16(sc[2*nb  ], ah, bl4.x, bl4.y);
                mma_bf16_16x8x16(sc[2*nb  ], al, bh4.x, bh4.y);
                mma_bf16_16x8x16(sc[2*nb+1], ah, bh4.z, bh4.w);
                mma_bf16_16x8x16(sc[2*nb+1], ah, bl4.z, bl4.w);
                mma_bf16_16x8x16(sc[2*nb+1], al, bh4.z, bh4.w);
            }
        }

        const int r0 = qs + wr + g;
        const int r1 = r0 + 8;
        const bool part = (ks + 31 > qs + wr);
        #pragma unroll
        for (int j = 0; j < 4; j++) {
            int cb = ks + j * 8 + 2 * tg;
            sc[j][0] = (part && cb     > r0) ? -1e30f : sc[j][0] * scale;
            sc[j][1] = (part && cb + 1 > r0) ? -1e30f : sc[j][1] * scale;
            sc[j][2] = (part && cb     > r1) ? -1e30f : sc[j][2] * scale;
            sc[j][3] = (part && cb + 1 > r1) ? -1e30f : sc[j][3] * scale;
        }

        #pragma unroll
        for (int j = 0; j < 4; j++) {
            sc[j][0] = __expf(sc[j][0]); l0s += sc[j][0];
            sc[j][1] = __expf(sc[j][1]); l0s += sc[j][1];
            sc[j][2] = __expf(sc[j][2]); l1s += sc[j][2];
            sc[j][3] = __expf(sc[j][3]); l1s += sc[j][3];
        }

        #pragma unroll
        for (int k2 = 0; k2 < 2; k2++) {
            uint32_t ah[4], al[4];
            split_bf2(sc[2*k2  ][0], sc[2*k2  ][1], ah[0], al[0]);
            split_bf2(sc[2*k2  ][2], sc[2*k2  ][3], ah[1], al[1]);
            split_bf2(sc[2*k2+1][0], sc[2*k2+1][1], ah[2], al[2]);
            split_bf2(sc[2*k2+1][2], sc[2*k2+1][3], ah[3], al[3]);
            #pragma unroll
            for (int dnb = 0; dnb < 8; dnb++) {
                uint4 vh4 = Vh4[(dnb * 2 + k2) * 32 + lane];
                uint4 vl4 = Vl4[(dnb * 2 + k2) * 32 + lane];
                mma_bf16_16x8x16(o[2*dnb  ], ah, vh4.x, vh4.y);
                mma_bf16_16x8x16(o[2*dnb  ], ah, vl4.x, vl4.y);
                mma_bf16_16x8x16(o[2*dnb  ], al, vh4.x, vh4.y);
                mma_bf16_16x8x16(o[2*dnb+1], ah, vh4.z, vh4.w);
                mma_bf16_16x8x16(o[2*dnb+1], ah, vl4.z, vl4.w);
                mma_bf16_16x8x16(o[2*dnb+1], al, vh4.z, vh4.w);
            }
        }

        __syncthreads();
        issueKV(kt + 2);
        cp_commit();
    }

    // reduce l over the tg quad (once)
    l0s += __shfl_xor_sync(0xffffffff, l0s, 1);
    l0s += __shfl_xor_sync(0xffffffff, l0s, 2);
    l1s += __shfl_xor_sync(0xffffffff, l1s, 1);
    l1s += __shfl_xor_sync(0xffffffff, l1s, 2);

    // ---- epilogue: ctx -> g_cp (tf32 bits, A-fragment-permuted) ----
    const float inv0 = 1.f / l0s;
    const float inv1 = 1.f / l1s;
    const int b = bh >> 4;
    const int h = bh & 15;
    const int m_blk = (b * SEQ + qs + wr) >> 4;
    const int lane0 = 4 * g + (tg & 1) * 2;
    const int w0 = (tg >> 1) * 2;
    #pragma unroll
    for (int jd = 0; jd < 16; jd++) {
        int kblk = h * 16 + jd;
        uint32_t* p = g_cp + (((size_t)m_blk * KBLKS + kblk) * 32 + lane0) * 4 + w0;
        *(uint2*)p       = make_uint2(f32_to_tf32(o[jd][0] * inv0), f32_to_tf32(o[jd][2] * inv1));
        *(uint2*)(p + 4) = make_uint2(f32_to_tf32(o[jd][1] * inv0), f32_to_tf32(o[jd][3] * inv1));
    }
}

// ---------------------------------------------------------------------------
extern "C" void kernel_launch(void* const* d_in, const int* in_sizes, int n_in,
                              void* d_out, int out_size)
{
    const float* x     = (const float*)d_in[0];
    const float* Wq    = (const float*)d_in[1];
    const float* Wk    = (const float*)d_in[2];
    const float* Wv    = (const float*)d_in[3];
    const float* Wo    = (const float*)d_in[4];
    const float* bo    = (const float*)d_in[5];
    const float* theta = (const float*)d_in[6];
    float* out = (float*)d_out;

    // 0. Convert + permute x and weights; build rope cos/sin table
    const size_t total_chunks = XCHUNKS + 4 * WCHUNKS;
    cvt_perm_kernel<<<(unsigned)(total_chunks / 256), 256>>>(x, Wq, Wk, Wv, Wo);
    rope_table_kernel<<<SEQ, 64>>>(theta);

    // 1. QKV projections (128x128 tiles, 3 CTAs/SM), scatter to [b,h,t,dh]
    cudaFuncSetAttribute(gemm_perm_kernel<0>, cudaFuncAttributeMaxDynamicSharedMemorySize, GEMM_SMEM);
    gemm_perm_kernel<0><<<dim3(DMODEL/128, NROWS/128, 3), 128, GEMM_SMEM>>>(nullptr, nullptr);

    // 2. RoPE -> fragment-permuted bf16 q/k;  V transpose+split (B-perm)
    rope_split_kernel<<<dim3(SEQ/4, BSZ*NHEADS, 2), dim3(64, 4)>>>();
    v_prep_kernel<<<dim3(SEQ/128, HDIM/32, BSZ*NHEADS), 256>>>();

    // 3. Causal flash attention (bf16x3, Q-hi in regs, 2-stage, 2 CTAs/SM)
    cudaFuncSetAttribute(attn_bf16_kernel, cudaFuncAttributeMaxDynamicSharedMemorySize, ATTN_SMEM_BYTES);
    attn_bf16_kernel<<<dim3(SEQ/64, BSZ*NHEADS), 128, ATTN_SMEM_BYTES>>>();

    // 4. Output projection + bias
    cudaFuncSetAttribute(gemm_perm_kernel<1>, cudaFuncAttributeMaxDynamicSharedMemorySize, GEMM_SMEM);
    gemm_perm_kernel<1><<<dim3(DMODEL/128, NROWS/128, 1), 128, GEMM_SMEM>>>(bo, out);
}

// round 15
// speedup vs baseline: 1.5490x; 1.0115x over previous
#include <cuda_runtime.h>
#include <cuda_bf16.h>
#include <math.h>
#include <stdint.h>

#define BSZ 2
#define SEQ 2048
#define DMODEL 2048
#define NHEADS 16
#define HDIM 128
#define NROWS (BSZ*SEQ)     // 4096
#define WSZ (DMODEL*DMODEL)
#define KBLKS (DMODEL/8)    // 256 k8-blocks per row
#define NB2T (DMODEL/16)    // 128 n16-blocks

// Scratch (allocation-free rule: __device__ globals)
__device__ float    g_v[BSZ*NHEADS*SEQ*HDIM];
__device__ uint32_t g_xp[(size_t)NROWS*DMODEL];   // x, tf32 bits, A-fragment-permuted
__device__ uint32_t g_wp[(size_t)4*WSZ];          // Wq,Wk,Wv,Wo tf32 bits, B-fragment-permuted
__device__ uint32_t g_cp[(size_t)NROWS*DMODEL];   // ctx, tf32 bits, A-fragment-permuted
// attention operands, pre-split bf16 hi/lo packed words, FRAGMENT-PERMUTED:
//   q: A-perm  [bh][mb16][kb8][lane][4w]
//   k: B-perm  [bh][nb16][kb8][lane][4w]
//   v: B-perm over d, k-dim = tpairs  [bh][dnb16][kb8][lane][4w]
__device__ uint32_t g_qh[(size_t)BSZ*NHEADS*SEQ*64];
__device__ uint32_t g_ql[(size_t)BSZ*NHEADS*SEQ*64];
__device__ uint32_t g_kh[(size_t)BSZ*NHEADS*SEQ*64];
__device__ uint32_t g_kl[(size_t)BSZ*NHEADS*SEQ*64];
__device__ uint32_t g_vth[(size_t)BSZ*NHEADS*HDIM*(SEQ/2)];
__device__ uint32_t g_vtl[(size_t)BSZ*NHEADS*HDIM*(SEQ/2)];
__device__ float2   g_rct[(size_t)SEQ*64];        // (cos, sin) per (t, d)

// ---------------------------------------------------------------------------
// helpers
// ---------------------------------------------------------------------------
__device__ __forceinline__ uint32_t f32_to_tf32(float f) {
    uint32_t r;
    asm("cvt.rna.tf32.f32 %0, %1;" : "=r"(r) : "f"(f));
    return r;
}

__device__ __forceinline__ void mma_tf32_16x8x8(float c[4], const uint32_t a[4], uint32_t b0, uint32_t b1) {
    asm volatile(
        "mma.sync.aligned.m16n8k8.row.col.f32.tf32.tf32.f32 "
        "{%0,%1,%2,%3}, {%4,%5,%6,%7}, {%8,%9}, {%0,%1,%2,%3};"
        : "+f"(c[0]), "+f"(c[1]), "+f"(c[2]), "+f"(c[3])
        : "r"(a[0]), "r"(a[1]), "r"(a[2]), "r"(a[3]), "r"(b0), "r"(b1));
}

__device__ __forceinline__ void mma_bf16_16x8x16(float c[4], const uint32_t a[4], uint32_t b0, uint32_t b1) {
    asm volatile(
        "mma.sync.aligned.m16n8k16.row.col.f32.bf16.bf16.f32 "
        "{%0,%1,%2,%3}, {%4,%5,%6,%7}, {%8,%9}, {%0,%1,%2,%3};"
        : "+f"(c[0]), "+f"(c[1]), "+f"(c[2]), "+f"(c[3])
        : "r"(a[0]), "r"(a[1]), "r"(a[2]), "r"(a[3]), "r"(b0), "r"(b1));
}

__device__ __forceinline__ uint32_t pack_bf2(float x, float y) {
    __nv_bfloat162 h = __float22bfloat162_rn(make_float2(x, y));
    return *(uint32_t*)&h;
}
__device__ __forceinline__ float bf2_lo_f32(uint32_t w) { return __uint_as_float(w << 16); }
__device__ __forceinline__ float bf2_hi_f32(uint32_t w) { return __uint_as_float(w & 0xffff0000u); }
__device__ __forceinline__ void split_bf2(float x, float y, uint32_t& hi, uint32_t& lo) {
    hi = pack_bf2(x, y);
    lo = pack_bf2(x - bf2_lo_f32(hi), y - bf2_hi_f32(hi));
}

__device__ __forceinline__ void cp16(void* dst, const void* src) {
    uint32_t s = (uint32_t)__cvta_generic_to_shared(dst);
    asm volatile("cp.async.cg.shared.global [%0], [%1], 16;" :: "r"(s), "l"(src));
}
__device__ __forceinline__ void cp_commit() { asm volatile("cp.async.commit_group;"); }
template<int N> __device__ __forceinline__ void cp_wait() { asm volatile("cp.async.wait_group %0;" :: "n"(N)); }

// ---------------------------------------------------------------------------
// Convert + permute x / weights to tf32 fragment layout (unchanged)
// ---------------------------------------------------------------------------
#define XCHUNKS ((size_t)(NROWS/16)*KBLKS*32)   // 2^21
#define WCHUNKS ((size_t)NB2T*KBLKS*32)         // 2^20

__global__ void cvt_perm_kernel(const float* __restrict__ x,
                                const float* __restrict__ Wq,
                                const float* __restrict__ Wk,
                                const float* __restrict__ Wv,
                                const float* __restrict__ Wo)
{
    size_t idx = (size_t)blockIdx.x * 256 + threadIdx.x;
    const int lane = (int)(idx & 31);
    const int g = lane >> 2, tg = lane & 3;
    uint4 o;
    if (idx < XCHUNKS) {
        int kb = (int)((idx >> 5) & (KBLKS - 1));
        int mb = (int)(idx >> 13);
        const float* s = x + (size_t)(mb * 16 + g) * DMODEL + kb * 8 + tg;
        o.x = f32_to_tf32(s[0]);
        o.y = f32_to_tf32(s[8 * DMODEL]);
        o.z = f32_to_tf32(s[4]);
        o.w = f32_to_tf32(s[8 * DMODEL + 4]);
        ((uint4*)g_xp)[idx] = o;
    } else {
        size_t j = idx - XCHUNKS;
        int wsel = (int)(j >> 20);
        size_t o2 = j & ((((size_t)1) << 20) - 1);
        int kb = (int)((o2 >> 5) & (KBLKS - 1));
        int nb2 = (int)(o2 >> 13);
        const float* W = (wsel == 0) ? Wq : (wsel == 1) ? Wk : (wsel == 2) ? Wv : Wo;
        const float* s = W + (size_t)(nb2 * 16 + g) * DMODEL + kb * 8 + tg;
        o.x = f32_to_tf32(s[0]);
        o.y = f32_to_tf32(s[4]);
        o.z = f32_to_tf32(s[8 * DMODEL]);
        o.w = f32_to_tf32(s[8 * DMODEL + 4]);
        ((uint4*)g_wp)[(size_t)wsel * WCHUNKS + o2] = o;
    }
}

// ---------------------------------------------------------------------------
// tf32 NT GEMM on fragment-permuted operands.
// MODE 0: z=0/1 -> Q/K with FUSED RoPE + bf16 split, written fragment-permuted;
//         z=2  -> V written f32 scatter to g_v [b,h,t,dh]
// MODE 1: A=g_cp, W=Wo, adds bias, writes f32 row-major to Cout
// ---------------------------------------------------------------------------
#define ABYTES (8*4*32*16)     // 16384
#define BBYTES (8*4*32*16)     // 16384
#define STGB   (ABYTES + BBYTES)   // 32768
#define NSTG 2
#define GEMM_SMEM (NSTG * STGB)    // 65536

template<int MODE>
__global__ void __launch_bounds__(128, 3) gemm_perm_kernel(
    const float* __restrict__ bias, float* __restrict__ Cout)
{
    extern __shared__ char sh[];

    const int tid  = threadIdx.x;
    const int lane = tid & 31;
    const int wrp  = tid >> 5;
    const int g    = lane >> 2;
    const int tg   = lane & 3;
    const int rh   = wrp >> 1;
    const int cw   = wrp & 1;

    const int rowBase = blockIdx.y * 128;
    const int colBase = blockIdx.x * 128;
    const int mb0  = blockIdx.y * 8;
    const int nb20 = blockIdx.x * 8;

    const uint32_t* Ag = (MODE == 0) ? g_xp : g_cp;
    const uint32_t* Bg = g_wp + (size_t)((MODE == 0) ? blockIdx.z : 3) * WSZ;

    auto issue = [&](int kt, int s) {
        char* st = sh + s * STGB;
        const int kb0 = kt * 4;
        #pragma unroll
        for (int p = 0; p < 8; p++) {
            int c = tid + p * 128;
            int mbL = c >> 7, kbL = (c >> 5) & 3, ln = c & 31;
            const uint32_t* gsrc = Ag + (((size_t)(mb0 + mbL) * KBLKS + kb0 + kbL) * 32 + ln) * 4;
            cp16(st + c * 16, gsrc);
        }
        #pragma unroll
        for (int p = 0; p < 8; p++) {
            int c = tid + p * 128;
            int nbL = c >> 7, kbL = (c >> 5) & 3, ln = c & 31;
            const uint32_t* gsrc = Bg + (((size_t)(nb20 + nbL) * KBLKS + kb0 + kbL) * 32 + ln) * 4;
            cp16(st + ABYTES + c * 16, gsrc);
        }
    };

    float acc[4][8][4];
    #pragma unroll
    for (int i = 0; i < 4; i++)
        #pragma unroll
        for (int j = 0; j < 8; j++)
            #pragma unroll
            for (int c = 0; c < 4; c++) acc[i][j][c] = 0.f;

    issue(0, 0); cp_commit();
    issue(1, 1); cp_commit();

    const int NKT = DMODEL / 32;
    for (int kt = 0; kt < NKT; kt++) {
        cp_wait<1>();
        __syncthreads();

        const char* st = sh + (kt & 1) * STGB;
        const uint4* As4 = (const uint4*)st;
        const uint4* Bs4 = (const uint4*)(st + ABYTES);

        #pragma unroll
        for (int kk = 0; kk < 4; kk++) {
            uint4 af[4];
            #pragma unroll
            for (int i = 0; i < 4; i++)
                af[i] = As4[((rh * 4 + i) * 4 + kk) * 32 + lane];
            #pragma unroll
            for (int j2 = 0; j2 < 4; j2++) {
                uint4 bv = Bs4[((cw * 4 + j2) * 4 + kk) * 32 + lane];
                #pragma unroll
                for (int i = 0; i < 4; i++) {
                    mma_tf32_16x8x8(acc[i][2*j2  ], (const uint32_t*)&af[i], bv.x, bv.y);
                    mma_tf32_16x8x8(acc[i][2*j2+1], (const uint32_t*)&af[i], bv.z, bv.w);
                }
            }
        }

        __syncthreads();
        if (kt + 2 < NKT) issue(kt + 2, kt & 1);
        cp_commit();
    }

    if (MODE == 0) {
        if (blockIdx.z < 2) {
            // ---- FUSED RoPE + bf16 split, write fragment-permuted q/k ----
            const bool isK = (blockIdx.z == 1);
            uint32_t* dH = isK ? g_kh : g_qh;
            uint32_t* dL = isK ? g_kl : g_ql;
            #pragma unroll
            for (int i = 0; i < 4; i++) {
                #pragma unroll
                for (int cc = 0; cc < 2; cc++) {
                    int m = rowBase + rh * 64 + i * 16 + g + cc * 8;
                    int b = m >> 11;
                    int t = m & (SEQ - 1);
                    int r16 = t & 15;
                    #pragma unroll
                    for (int j = 0; j < 8; j++) {
                        int n0 = colBase + cw * 64 + j * 8 + tg * 2;
                        int h  = n0 >> 7;
                        int dp = (n0 & (HDIM - 1)) >> 1;   // rope pair index 0..63
                        float2 cs = g_rct[(size_t)t * 64 + dp];
                        float ve = acc[i][j][cc * 2 + 0];
                        float vo = acc[i][j][cc * 2 + 1];
                        float olo = ve * cs.x - vo * cs.y;   // out[dp]
                        float ohi = ve * cs.y + vo * cs.x;   // out[64+dp]
                        float plo = __shfl_xor_sync(0xffffffff, olo, 1);
                        float phi = __shfl_xor_sync(0xffffffff, ohi, 1);
                        if ((tg & 1) == 0) {
                            int bh2 = b * NHEADS + h;
                            size_t cb = (size_t)(bh2 * 128 + (t >> 4));
                            uint32_t hi, lo;
                            // low-half word: jw = dp>>1
                            int jw = dp >> 1;
                            int lane2 = (r16 & 7) * 4 + (jw & 3);
                            int w = isK ? (((jw >> 2) & 1) | ((r16 >> 3) << 1))
                                        : ((r16 >> 3) | (((jw >> 2) & 1) << 1));
                            size_t word = ((cb * 8 + (jw >> 3)) * 32 + lane2) * 4 + w;
                            split_bf2(olo, plo, hi, lo);
                            dH[word] = hi; dL[word] = lo;
                            // high-half word: jw + 32
                            jw += 32;
                            lane2 = (r16 & 7) * 4 + (jw & 3);
                            w = isK ? (((jw >> 2) & 1) | ((r16 >> 3) << 1))
                                    : ((r16 >> 3) | (((jw >> 2) & 1) << 1));
                            word = ((cb * 8 + (jw >> 3)) * 32 + lane2) * 4 + w;
                            split_bf2(ohi, phi, hi, lo);
                            dH[word] = hi; dL[word] = lo;
                        }
                    }
                }
            }
        } else {
            // ---- V: f32 scatter to g_v [b,h,t,dh] ----
            #pragma unroll
            for (int i = 0; i < 4; i++) {
                #pragma unroll
                for (int cc = 0; cc < 2; cc++) {
                    int m = rowBase + rh * 64 + i * 16 + g + cc * 8;
                    int b = m >> 11;
                    int t = m & (SEQ - 1);
                    size_t rowoff = ((size_t)(b * NHEADS) * SEQ + t) << 7;
                    #pragma unroll
                    for (int j = 0; j < 8; j++) {
                        int n0 = colBase + cw * 64 + j * 8 + tg * 2;
                        int h  = n0 >> 7;
                        int dh2 = n0 & (HDIM - 1);
                        float* dst = g_v + rowoff + (((size_t)h * SEQ) << 7) + dh2;
                        dst[0] = acc[i][j][cc * 2 + 0];
                        dst[1] = acc[i][j][cc * 2 + 1];
                    }
                }
            }
        }
    } else {
        #pragma unroll
        for (int i = 0; i < 4; i++) {
            #pragma unroll
            for (int cc = 0; cc < 2; cc++) {
                int m = rowBase + rh * 64 + i * 16 + g + cc * 8;
                #pragma unroll
                for (int j = 0; j < 8; j++) {
                    int n0 = colBase + cw * 64 + j * 8 + tg * 2;
                    float2 v;
                    v.x = acc[i][j][cc * 2 + 0] + bias[n0];
                    v.y = acc[i][j][cc * 2 + 1] + bias[n0 + 1];
                    *(float2*)(Cout + (size_t)m * DMODEL + n0) = v;
                }
            }
        }
    }
}

// ---------------------------------------------------------------------------
// RoPE cos/sin table
// ---------------------------------------------------------------------------
__global__ void rope_table_kernel(const float* __restrict__ theta)
{
    int t = blockIdx.x;
    int d = threadIdx.x;   // 0..63
    float s, c;
    sincosf((float)t * theta[d], &s, &c);
    g_rct[(size_t)t * 64 + d] = make_float2(c, s);
}

// ---------------------------------------------------------------------------
// V prep: transpose + split V, written B-perm over d (unchanged).
// ---------------------------------------------------------------------------
__global__ void __launch_bounds__(256) v_prep_kernel()
{
    __shared__ float sm[128 * 37];
    const int tid = threadIdx.x;
    const int t0 = blockIdx.x * 128;
    const int d0 = blockIdx.y * 32;
    const int bh = blockIdx.z;
    const float* src = g_v + ((size_t)bh * SEQ + t0) * HDIM + d0;

    #pragma unroll
    for (int p = 0; p < 4; p++) {
        int c = tid + p * 256;
        int t = c >> 3;
        int q = (c & 7) * 4;
        float4 v = *(const float4*)(src + (size_t)t * HDIM + q);
        float* d = sm + t * 37 + q;
        d[0] = v.x; d[1] = v.y; d[2] = v.z; d[3] = v.w;
    }
    __syncthreads();

    #pragma unroll
    for (int p = 0; p < 8; p++) {
        int wi = tid + p * 256;
        int dl = wi >> 6;                 // 0..31 local d
        int tpl = wi & 63;                // 0..63 local tpair
        uint32_t hi, lo;
        split_bf2(sm[(2*tpl) * 37 + dl], sm[(2*tpl + 1) * 37 + dl], hi, lo);

        int dg = d0 + dl;
        int tpg = t0 / 2 + tpl;
        int lane2 = (dg & 7) * 4 + (tpg & 3);
        int w = ((tpg >> 2) & 1) | (((dg & 15) >> 3) << 1);
        size_t word = (((size_t)(bh * 8 + (dg >> 4)) * 128 + (tpg >> 3)) * 32 + lane2) * 4 + w;
        g_vth[word] = hi;
        g_vtl[word] = lo;
    }
}

// ---------------------------------------------------------------------------
// Tensor-core flash attention (bf16x3), causal, fragment-permuted operands.
// R14 proven: Q-hi in regs, Q-lo in smem, 2-stage KV, 2 CTAs/SM.
// ---------------------------------------------------------------------------
#define AQLO 0
#define AST0 4096
#define ASTSZ 8192
#define AKHI 0
#define AKLO 2048
#define AVHI 4096
#define AVLO 6144
#define ATTN_SMEM_BYTES ((AST0 + 2*ASTSZ) * 4)   // 81920

__global__ void __launch_bounds__(128, 2) attn_bf16_kernel()
{
    extern __shared__ uint32_t sm[];

    const int tid  = threadIdx.x;
    const int lane = tid & 31;
    const int wrp  = tid >> 5;      // 0..3
    const int g    = lane >> 2;
    const int tg   = lane & 3;
    const int wr   = wrp * 16;

    const int qt = gridDim.x - 1 - blockIdx.x;   // big tiles first
    const int bh = blockIdx.y;
    const int qs = qt * 64;
    const float scale = 0.08838834764831845f;
    const int ktiles = 2 * qt + 2;               // 32-wide k tiles

    const uint4* Qg4  = (const uint4*)g_qh + (size_t)(bh * 128) * 8 * 32;
    const uint4* QgL4 = (const uint4*)g_ql + (size_t)(bh * 128) * 8 * 32;
    const uint4* Kg4  = (const uint4*)g_kh + (size_t)(bh * 128) * 8 * 32;
    const uint4* KgL4 = (const uint4*)g_kl + (size_t)(bh * 128) * 8 * 32;
    const uint4* Vg4  = (const uint4*)g_vth + (size_t)(bh * 8) * 128 * 32;
    const uint4* VgL4 = (const uint4*)g_vtl + (size_t)(bh * 8) * 128 * 32;

    // Q-hi fragments: each warp loads its own 16 rows once into registers
    uint4 qh4[8];
    #pragma unroll
    for (int kk = 0; kk < 8; kk++)
        qh4[kk] = Qg4[((size_t)(qt * 4 + wrp) * 8 + kk) * 32 + lane];

    auto issueKV = [&](int kt) {
        if (kt >= ktiles) return;
        uint32_t* st = sm + AST0 + (kt & 1) * ASTSZ;
        #pragma unroll
        for (int p = 0; p < 4; p++) {                  // K: 512 chunks
            int c = tid + p * 128;
            int nbL = c >> 8, kbL = (c >> 5) & 7, ln = c & 31;
            cp16(st + AKHI + c * 4, Kg4 + ((size_t)(kt * 2 + nbL) * 8 + kbL) * 32 + ln);
            cp16(st + AKLO + c * 4, KgL4 + ((size_t)(kt * 2 + nbL) * 8 + kbL) * 32 + ln);
        }
        #pragma unroll
        for (int p = 0; p < 4; p++) {                  // V: 512 chunks
            int c = tid + p * 128;
            int dnbL = c >> 6, kbL = (c >> 5) & 1, ln = c & 31;
            cp16(st + AVHI + c * 4, Vg4 + ((size_t)dnbL * 128 + kt * 2 + kbL) * 32 + ln);
            cp16(st + AVLO + c * 4, VgL4 + ((size_t)dnbL * 128 + kt * 2 + kbL) * 32 + ln);
        }
    };

    // Q-lo load (once): 1024 chunks (4 mb x 8 kb x 32)
    #pragma unroll
    for (int p = 0; p < 8; p++) {
        int c = tid + p * 128;
        int mbL = c >> 8, kbL = (c >> 5) & 7, ln = c & 31;
        cp16(sm + AQLO + c * 4, QgL4 + ((size_t)(qt * 4 + mbL) * 8 + kbL) * 32 + ln);
    }
    issueKV(0); cp_commit();
    issueKV(1); cp_commit();

    float o[16][4];
    #pragma unroll
    for (int j = 0; j < 16; j++)
        #pragma unroll
        for (int c = 0; c < 4; c++) o[j][c] = 0.f;
    float l0s = 0.f, l1s = 0.f;

    for (int kt = 0; kt < ktiles; kt++) {
        const int ks = kt * 32;
        cp_wait<1>();
        __syncthreads();

        const uint4* Kh4 = (const uint4*)(sm + AST0 + (kt & 1) * ASTSZ + AKHI);
        const uint4* Kl4 = (const uint4*)(sm + AST0 + (kt & 1) * ASTSZ + AKLO);
        const uint4* Vh4 = (const uint4*)(sm + AST0 + (kt & 1) * ASTSZ + AVHI);
        const uint4* Vl4 = (const uint4*)(sm + AST0 + (kt & 1) * ASTSZ + AVLO);
        const uint4* Ql4 = (const uint4*)(sm + AQLO);

        float sc[4][4];
        #pragma unroll
        for (int j = 0; j < 4; j++)
            #pragma unroll
            for (int c = 0; c < 4; c++) sc[j][c] = 0.f;

        #pragma unroll
        for (int kk = 0; kk < 8; kk++) {
            uint4 al4 = Ql4[(wrp * 8 + kk) * 32 + lane];
            const uint32_t* ah = (const uint32_t*)&qh4[kk];
            const uint32_t* al = (const uint32_t*)&al4;
            #pragma unroll
            for (int nb = 0; nb < 2; nb++) {
                uint4 bh4 = Kh4[(nb * 8 + kk) * 32 + lane];
                uint4 bl4 = Kl4[(nb * 8 + kk) * 32 + lane];
                mma_bf16_16x8x16(sc[2*nb  ], ah, bh4.x, bh4.y);
                mma_bf16_16x8x16(sc[2*nb  ], ah, bl4.x, bl4.y);
                mma_bf16_16x8x16(sc[2*nb  ], al, bh4.x, bh4.y);
                mma_bf16_16x8x16(sc[2*nb+1], ah, bh4.z, bh4.w);
                mma_bf16_16x8x16(sc[2*nb+1], ah, bl4.z, bl4.w);
                mma_bf16_16x8x16(sc[2*nb+1], al, bh4.z, bh4.w);
            }
        }

        const int r0 = qs + wr + g;
        const int r1 = r0 + 8;
        const bool part = (ks + 31 > qs + wr);
        #pragma unroll
        for (int j = 0; j < 4; j++) {
            int cb = ks + j * 8 + 2 * tg;
            sc[j][0] = (part && cb     > r0) ? -1e30f : sc[j][0] * scale;
            sc[j][1] = (part && cb + 1 > r0) ? -1e30f : sc[j][1] * scale;
            sc[j][2] = (part && cb     > r1) ? -1e30f : sc[j][2] * scale;
            sc[j][3] = (part && cb + 1 > r1) ? -1e30f : sc[j][3] * scale;
        }

        #pragma unroll
        for (int j = 0; j < 4; j++) {
            sc[j][0] = __expf(sc[j][0]); l0s += sc[j][0];
            sc[j][1] = __expf(sc[j][1]); l0s += sc[j][1];
            sc[j][2] = __expf(sc[j][2]); l1s += sc[j][2];
            sc[j][3] = __expf(sc[j][3]); l1s += sc[j][3];
        }

        #pragma unroll
        for (int k2 = 0; k2 < 2; k2++) {
            uint32_t ah[4], al[4];
            split_bf2(sc[2*k2  ][0], sc[2*k2  ][1], ah[0], al[0]);
            split_bf2(sc[2*k2  ][2], sc[2*k2  ][3], ah[1], al[1]);
            split_bf2(sc[2*k2+1][0], sc[2*k2+1][1], ah[2], al[2]);
            split_bf2(sc[2*k2+1][2], sc[2*k2+1][3], ah[3], al[3]);
            #pragma unroll
            for (int dnb = 0; dnb < 8; dnb++) {
                uint4 vh4 = Vh4[(dnb * 2 + k2) * 32 + lane];
                uint4 vl4 = Vl4[(dnb * 2 + k2) * 32 + lane];
                mma_bf16_16x8x16(o[2*dnb  ], ah, vh4.x, vh4.y);
                mma_bf16_16x8x16(o[2*dnb  ], ah, vl4.x, vl4.y);
                mma_bf16_16x8x16(o[2*dnb  ], al, vh4.x, vh4.y);
                mma_bf16_16x8x16(o[2*dnb+1], ah, vh4.z, vh4.w);
                mma_bf16_16x8x16(o[2*dnb+1], ah, vl4.z, vl4.w);
                mma_bf16_16x8x16(o[2*dnb+1], al, vh4.z, vh4.w);
            }
        }

        __syncthreads();
        issueKV(kt + 2);
        cp_commit();
    }

    // reduce l over the tg quad (once)
    l0s += __shfl_xor_sync(0xffffffff, l0s, 1);
    l0s += __shfl_xor_sync(0xffffffff, l0s, 2);
    l1s += __shfl_xor_sync(0xffffffff, l1s, 1);
    l1s += __shfl_xor_sync(0xffffffff, l1s, 2);

    // ---- epilogue: ctx -> g_cp (tf32 bits, A-fragment-permuted) ----
    const float inv0 = 1.f / l0s;
    const float inv1 = 1.f / l1s;
    const int b = bh >> 4;
    const int h = bh & 15;
    const int m_blk = (b * SEQ + qs + wr) >> 4;
    const int lane0 = 4 * g + (tg & 1) * 2;
    const int w0 = (tg >> 1) * 2;
    #pragma unroll
    for (int jd = 0; jd < 16; jd++) {
        int kblk = h * 16 + jd;
        uint32_t* p = g_cp + (((size_t)m_blk * KBLKS + kblk) * 32 + lane0) * 4 + w0;
        *(uint2*)p       = make_uint2(f32_to_tf32(o[jd][0] * inv0), f32_to_tf32(o[jd][2] * inv1));
        *(uint2*)(p + 4) = make_uint2(f32_to_tf32(o[jd][1] * inv0), f32_to_tf32(o[jd][3] * inv1));
    }
}

// ---------------------------------------------------------------------------
extern "C" void kernel_launch(void* const* d_in, const int* in_sizes, int n_in,
                              void* d_out, int out_size)
{
    const float* x     = (const float*)d_in[0];
    const float* Wq    = (const float*)d_in[1];
    const float* Wk    = (const float*)d_in[2];
    const float* Wv    = (const float*)d_in[3];
    const float* Wo    = (const float*)d_in[4];
    const float* bo    = (const float*)d_in[5];
    const float* theta = (const float*)d_in[6];
    float* out = (float*)d_out;

    // 0. Convert + permute x and weights; build rope cos/sin table
    const size_t total_chunks = XCHUNKS + 4 * WCHUNKS;
    cvt_perm_kernel<<<(unsigned)(total_chunks / 256), 256>>>(x, Wq, Wk, Wv, Wo);
    rope_table_kernel<<<SEQ, 64>>>(theta);

    // 1. QKV projections; Q/K epilogue fuses RoPE + bf16 split (perm layout),
    //    V written f32 to g_v
    cudaFuncSetAttribute(gemm_perm_kernel<0>, cudaFuncAttributeMaxDynamicSharedMemorySize, GEMM_SMEM);
    gemm_perm_kernel<0><<<dim3(DMODEL/128, NROWS/128, 3), 128, GEMM_SMEM>>>(nullptr, nullptr);

    // 2. V transpose + split (B-perm)
    v_prep_kernel<<<dim3(SEQ/128, HDIM/32, BSZ*NHEADS), 256>>>();

    // 3. Causal flash attention (bf16x3, Q-hi in regs, 2-stage, 2 CTAs/SM)
    cudaFuncSetAttribute(attn_bf16_kernel, cudaFuncAttributeMaxDynamicSharedMemorySize, ATTN_SMEM_BYTES);
    attn_bf16_kernel<<<dim3(SEQ/64, BSZ*NHEADS), 128, ATTN_SMEM_BYTES>>>();

    // 4. Output projection + bias
    cudaFuncSetAttribute(gemm_perm_kernel<1>, cudaFuncAttributeMaxDynamicSharedMemorySize, GEMM_SMEM);
    gemm_perm_kernel<1><<<dim3(DMODEL/128, NROWS/128, 1), 128, GEMM_SMEM>>>(bo, out);
}